// round 7
// baseline (speedup 1.0000x reference)
#include <cuda_runtime.h>
#include <cstdint>

#define HH 2160
#define WW 3840
#define NS 512
#define ADJ_ELEMS (NS * NS)

#define TILE_W 128
#define TILE_H 48
#define SUB_H  16
#define NSUB   (TILE_H / SUB_H)
#define NBLK   ((WW / TILE_W) * (HH / TILE_H))   // 1350

// Global accumulators: g_a[s] = (cnt << 40) | sum_y ; g_b[s] = sum_x
__device__ unsigned long long g_a[NS];
__device__ unsigned long long g_b[NS];
__device__ unsigned int g_done;

// ---------------------------------------------------------------------------
// Kernel 1: zero adjacency region (vectorized) + accumulators + counter.
// ---------------------------------------------------------------------------
__global__ void zero_kernel(float4* __restrict__ out) {
    int idx = blockIdx.x * blockDim.x + threadIdx.x;   // 65536 float4 = 1MB
    out[idx] = make_float4(0.f, 0.f, 0.f, 0.f);
    if (idx < NS) { g_a[idx] = 0ULL; g_b[idx] = 0ULL; }
    if (idx == 0) g_done = 0u;
}

// ---------------------------------------------------------------------------
// Kernel 2: main scan + (last block) centers.
// 512 threads; warp w handles row (sub*16 + w) of each 128x16 sub-tile;
// lane l handles 4 consecutive pixels via one int4 load.
//
// Histogram: ONE packed-u32 shared atomic per pixel:
//   bits [0:7) count | [7:18) sum_dy (dy=warp 0..15) | [18:32) sum_dx (0..127)
// Double-buffered (hist[sub&1]) so each sub-tile needs only ONE barrier:
// buffer p is flushed+zeroed right after the barrier of sub-tile p and not
// written again until sub-tile p+2, whose adds are ordered by the barrier
// of sub-tile p+1.
//
// Adjacency: idempotent __stcg 1.0f stores; borders replicate -> equal -> skip.
// ---------------------------------------------------------------------------
__global__ __launch_bounds__(512) void main_kernel(const int* __restrict__ seg,
                                                   float* __restrict__ out) {
    __shared__ unsigned int hist[2][NS];
    __shared__ unsigned int is_last;
    float* const adj = out;
    const int t    = threadIdx.x;
    const int lane = t & 31;
    const int wrp  = t >> 5;                 // 0..15 : row within sub-tile (dy)
    const int x0   = blockIdx.x * TILE_W;
    const int y0   = blockIdx.y * TILE_H;

    hist[0][t & (NS - 1)] = 0u;              // t<512 covers both buffers:
    hist[1][t & (NS - 1)] = 0u;
    unsigned int cnt_r = 0u, sx_r = 0u, sy_r = 0u;
    __syncthreads();

    const int xg = x0 + lane * 4;
    const unsigned int dy_pack = 1u | ((unsigned int)wrp << 7);

#pragma unroll
    for (int sub = 0; sub < NSUB; ++sub) {
        const int yg = y0 + sub * SUB_H + wrp;
        const int* row = seg + (size_t)yg * WW + xg;
        unsigned int* const hb = hist[sub & 1];

        const int4 self = *(const int4*)row;

        // Right neighbor of element 3 = next lane's element 0.
        int nr = __shfl_down_sync(0xffffffffu, self.x, 1);
        if (lane == 31)
            nr = (xg + 4 < WW) ? row[4] : self.w;   // replicate at x edge

        int4 dn;
        if (yg + 1 < HH) dn = *(const int4*)(row + WW);
        else             dn = self;                  // replicate at y edge

        const int sv[4] = {self.x, self.y, self.z, self.w};
        const int rv[4] = {self.y, self.z, self.w, nr};
        const int dv[4] = {dn.x, dn.y, dn.z, dn.w};

#pragma unroll
        for (int j = 0; j < 4; ++j) {
            const int s = sv[j];
            const unsigned int dx = (unsigned int)(lane * 4 + j);
            atomicAdd(&hb[s], dy_pack + (dx << 18));
            const int base = s * NS;
            if (s != rv[j]) __stcg(&adj[base + rv[j]], 1.0f);
            if (s != dv[j]) __stcg(&adj[base + dv[j]], 1.0f);
        }

        __syncthreads();                     // all adds to hb done
        {
            const unsigned int v = hb[t];
            hb[t] = 0u;                      // safe: hb reused at sub+2,
            const unsigned int c = v & 127u; // ordered by sub+1's barrier
            cnt_r += c;
            sy_r  += ((v >> 7) & 0x7FFu) + c * (unsigned int)(sub * SUB_H);
            sx_r  += v >> 18;
        }
    }

    // Per-block flush: 2 u64 REDG per bin.
    const unsigned long long sy_abs =
        (unsigned long long)sy_r + (unsigned long long)cnt_r * (unsigned long long)y0;
    const unsigned long long sx_abs =
        (unsigned long long)sx_r + (unsigned long long)cnt_r * (unsigned long long)x0;
    atomicAdd(&g_a[t], ((unsigned long long)cnt_r << 40) | sy_abs);
    atomicAdd(&g_b[t], sx_abs);

    // ---- last-block-done: compute centers in the final block ----
    __threadfence();                         // make this thread's REDG visible
    __syncthreads();                         // all threads' REDG fenced
    if (t == 0)
        is_last = (atomicAdd(&g_done, 1u) == NBLK - 1u) ? 1u : 0u;
    __syncthreads();
    if (is_last) {
        __threadfence();                     // acquire: see all blocks' REDG
        const unsigned long long a = __ldcg(&g_a[t]);
        const unsigned long long b = __ldcg(&g_b[t]);
        const double c  = (double)(a >> 40);
        const double sy = (double)(a & ((1ULL << 40) - 1ULL));
        out[ADJ_ELEMS + 2 * t + 0] = (float)((double)b / c);
        out[ADJ_ELEMS + 2 * t + 1] = (float)(sy / c);
    }
}

extern "C" void kernel_launch(void* const* d_in, const int* in_sizes, int n_in,
                              void* d_out, int out_size) {
    const int* seg = (const int*)d_in[0];
    float* out = (float*)d_out;

    zero_kernel<<<ADJ_ELEMS / 4 / 256, 256>>>((float4*)out);

    dim3 grid(WW / TILE_W, HH / TILE_H);   // 30 x 45 = 1350 blocks
    main_kernel<<<grid, 512>>>(seg, out);
}